// round 1
// baseline (speedup 1.0000x reference)
#include <cuda_runtime.h>
#include <math_constants.h>

// Problem constants
#define EMB   1024
#define HEADS 16
#define HD    64
#define BATCH 2
#define SEQ   2048
#define M_TOT (BATCH * SEQ)   // 4096 rows for the projection GEMMs

// Scratch (allocation-free rule: __device__ globals)
__device__ float g_Q[(size_t)BATCH * HEADS * SEQ * HD];   // [b*H+h][n][d]
__device__ float g_K[(size_t)BATCH * HEADS * SEQ * HD];
__device__ float g_V[(size_t)BATCH * HEADS * SEQ * HD];
__device__ float g_ctx[(size_t)M_TOT * EMB];              // [b*SEQ+n][e]

// ---------------------------------------------------------------------------
// Projection GEMM: out = X[M_TOT,EMB] @ W[EMB,EMB] + bias
// Block tile 128x128, K-step 16, 256 threads, 8x8 per-thread microtile.
// SPLIT=true  -> scatter into [b*H+h][n][d] head-major layout (for Q/K/V)
// SPLIT=false -> plain row-major [row][col] (final output projection)
// ---------------------------------------------------------------------------
template <bool SPLIT>
__global__ __launch_bounds__(256, 2)
void proj_kernel(const float* __restrict__ X,
                 const float* __restrict__ W,
                 const float* __restrict__ bias,
                 float* __restrict__ out)
{
    __shared__ float As[16][128];   // A transposed: As[k][m]
    __shared__ float Bs[16][128];   // Bs[k][n]

    const int tid = threadIdx.x;
    const int m0 = blockIdx.y * 128;
    const int n0 = blockIdx.x * 128;
    const int tm = tid >> 4;        // 0..15
    const int tn = tid & 15;        // 0..15

    float acc[8][8];
#pragma unroll
    for (int i = 0; i < 8; ++i)
#pragma unroll
        for (int j = 0; j < 8; ++j) acc[i][j] = 0.f;

    for (int k0 = 0; k0 < EMB; k0 += 16) {
        // Load A tile (128 x 16): 512 float4, 2 per thread, store transposed
#pragma unroll
        for (int u = 0; u < 2; ++u) {
            int id = tid * 2 + u;
            int r  = id >> 2;
            int c4 = (id & 3) * 4;
            float4 v = *(const float4*)(X + (size_t)(m0 + r) * EMB + k0 + c4);
            As[c4 + 0][r] = v.x;
            As[c4 + 1][r] = v.y;
            As[c4 + 2][r] = v.z;
            As[c4 + 3][r] = v.w;
        }
        // Load B tile (16 x 128): 512 float4, 2 per thread
#pragma unroll
        for (int u = 0; u < 2; ++u) {
            int id = tid * 2 + u;
            int r  = id >> 5;
            int c4 = (id & 31) * 4;
            *(float4*)(&Bs[r][c4]) =
                *(const float4*)(W + (size_t)(k0 + r) * EMB + n0 + c4);
        }
        __syncthreads();

#pragma unroll
        for (int kk = 0; kk < 16; ++kk) {
            float a[8], b[8];
            *(float4*)(a)     = *(const float4*)(&As[kk][tm * 8]);
            *(float4*)(a + 4) = *(const float4*)(&As[kk][tm * 8 + 4]);
            *(float4*)(b)     = *(const float4*)(&Bs[kk][tn * 8]);
            *(float4*)(b + 4) = *(const float4*)(&Bs[kk][tn * 8 + 4]);
#pragma unroll
            for (int i = 0; i < 8; ++i)
#pragma unroll
                for (int j = 0; j < 8; ++j)
                    acc[i][j] = fmaf(a[i], b[j], acc[i][j]);
        }
        __syncthreads();
    }

    // Epilogue: bias + (optional) head scatter
#pragma unroll
    for (int i = 0; i < 8; ++i) {
        const int row = m0 + tm * 8 + i;
        const int b   = row >> 11;            // /SEQ
        const int n   = row & (SEQ - 1);
#pragma unroll
        for (int j = 0; j < 8; ++j) {
            const int col = n0 + tn * 8 + j;
            const float v = acc[i][j] + __ldg(&bias[col]);
            if (SPLIT) {
                const int h  = col >> 6;      // /HD
                const int dd = col & (HD - 1);
                out[((size_t)(b * HEADS + h) * SEQ + n) * HD + dd] = v;
            } else {
                out[(size_t)row * EMB + col] = v;
            }
        }
    }
}

// ---------------------------------------------------------------------------
// Fused flash attention (fp32, online softmax).
// Grid: (SEQ/64, BATCH*HEADS). Block: 256 threads.
// Each block: one (b,h), 64 query rows. 4 threads ("quads") per query row,
// each quad thread owns a 16-wide slice of head dim. K/V tiles (64x64) in smem.
// Scores reduced across the quad with shfl.
// ---------------------------------------------------------------------------
__global__ __launch_bounds__(256, 2)
void attn_kernel(const float* __restrict__ Q,
                 const float* __restrict__ K,
                 const float* __restrict__ V,
                 float* __restrict__ ctx)
{
    __shared__ float Ks[64 * 64];
    __shared__ float Vs[64 * 64];

    const int tid = threadIdx.x;
    const int bh  = blockIdx.y;           // 0..31  (b*HEADS + h)
    const int q0  = blockIdx.x * 64;
    const int r   = tid >> 2;             // query row within tile, 0..63
    const int qd  = tid & 3;              // quad lane -> 16-col slice of d

    const float scale = 0.03125f;         // 1/sqrt(EMB) = 1/32

    const float* Qb = Q + (size_t)bh * SEQ * HD;
    const float* Kb = K + (size_t)bh * SEQ * HD;
    const float* Vb = V + (size_t)bh * SEQ * HD;

    // Load this thread's query fragment (pre-scaled)
    float qf[16];
    {
        const float* qp = Qb + (size_t)(q0 + r) * HD + qd * 16;
#pragma unroll
        for (int u = 0; u < 4; ++u) {
            float4 v = *(const float4*)(qp + u * 4);
            qf[u * 4 + 0] = v.x * scale;
            qf[u * 4 + 1] = v.y * scale;
            qf[u * 4 + 2] = v.z * scale;
            qf[u * 4 + 3] = v.w * scale;
        }
    }

    float acc[16];
#pragma unroll
    for (int i = 0; i < 16; ++i) acc[i] = 0.f;
    float m = -1e30f;
    float l = 0.f;

    for (int kt = 0; kt < SEQ; kt += 64) {
        // K/V tiles are contiguous 4096-float chunks: fully coalesced copy
        const float4* ksrc = (const float4*)(Kb + (size_t)kt * HD);
        const float4* vsrc = (const float4*)(Vb + (size_t)kt * HD);
#pragma unroll
        for (int u = 0; u < 4; ++u) {
            ((float4*)Ks)[tid + 256 * u] = ksrc[tid + 256 * u];
            ((float4*)Vs)[tid + 256 * u] = vsrc[tid + 256 * u];
        }
        __syncthreads();

        // 4 chunks of 16 keys each (keeps score regs at 16)
#pragma unroll
        for (int jc = 0; jc < 4; ++jc) {
            float s[16];
#pragma unroll
            for (int j = 0; j < 16; ++j) {
                const float* kr = &Ks[(jc * 16 + j) * 64 + qd * 16];
                float p = 0.f;
#pragma unroll
                for (int i = 0; i < 16; ++i) p = fmaf(qf[i], kr[i], p);
                // reduce partial dot across the 4 quad lanes
                p += __shfl_xor_sync(0xffffffffu, p, 1);
                p += __shfl_xor_sync(0xffffffffu, p, 2);
                s[j] = p;
            }

            float cm = s[0];
#pragma unroll
            for (int j = 1; j < 16; ++j) cm = fmaxf(cm, s[j]);
            const float mn = fmaxf(m, cm);
            const float f  = __expf(m - mn);

            float sp = 0.f;
#pragma unroll
            for (int j = 0; j < 16; ++j) {
                s[j] = __expf(s[j] - mn);
                sp += s[j];
            }
            l = l * f + sp;
            m = mn;

#pragma unroll
            for (int i = 0; i < 16; ++i) acc[i] *= f;
#pragma unroll
            for (int j = 0; j < 16; ++j) {
                const float* vr = &Vs[(jc * 16 + j) * 64 + qd * 16];
                const float pj = s[j];
#pragma unroll
                for (int i = 0; i < 16; ++i)
                    acc[i] = fmaf(pj, vr[i], acc[i]);
            }
        }
        __syncthreads();
    }

    const float inv = 1.f / l;
    const int b = bh / HEADS;
    const int h = bh % HEADS;
    // ctx layout: [b*SEQ+n][h*HD + dd]  (row-major, ready for the O-projection)
    float* op = ctx + (size_t)(b * SEQ + q0 + r) * EMB + h * HD + qd * 16;
#pragma unroll
    for (int u = 0; u < 4; ++u) {
        float4 v;
        v.x = acc[u * 4 + 0] * inv;
        v.y = acc[u * 4 + 1] * inv;
        v.z = acc[u * 4 + 2] * inv;
        v.w = acc[u * 4 + 3] * inv;
        ((float4*)op)[u] = v;
    }
}

// ---------------------------------------------------------------------------
// Launch
// ---------------------------------------------------------------------------
extern "C" void kernel_launch(void* const* d_in, const int* in_sizes, int n_in,
                              void* d_out, int out_size)
{
    const float* x  = (const float*)d_in[0];
    const float* Wq = (const float*)d_in[1];
    const float* bq = (const float*)d_in[2];
    const float* Wk = (const float*)d_in[3];
    const float* bk = (const float*)d_in[4];
    const float* Wv = (const float*)d_in[5];
    const float* bv = (const float*)d_in[6];
    const float* Wo = (const float*)d_in[7];
    const float* bo = (const float*)d_in[8];
    float* out = (float*)d_out;

    float *Qp, *Kp, *Vp, *Cp;
    cudaGetSymbolAddress((void**)&Qp, g_Q);
    cudaGetSymbolAddress((void**)&Kp, g_K);
    cudaGetSymbolAddress((void**)&Vp, g_V);
    cudaGetSymbolAddress((void**)&Cp, g_ctx);

    dim3 pgrid(EMB / 128, M_TOT / 128);   // (8, 32)
    proj_kernel<true><<<pgrid, 256>>>(x, Wq, bq, Qp);
    proj_kernel<true><<<pgrid, 256>>>(x, Wk, bk, Kp);
    proj_kernel<true><<<pgrid, 256>>>(x, Wv, bv, Vp);

    dim3 agrid(SEQ / 64, BATCH * HEADS);  // (32, 32)
    attn_kernel<<<agrid, 256>>>(Qp, Kp, Vp, Cp);

    proj_kernel<false><<<pgrid, 256>>>(Cp, Wo, bo, out);
}

// round 2
// speedup vs baseline: 2.5915x; 2.5915x over previous
#include <cuda_runtime.h>
#include <math_constants.h>

// Problem constants
#define EMB   1024
#define HEADS 16
#define HD    64
#define BATCH 2
#define SEQ   2048
#define M_TOT (BATCH * SEQ)

// Attention tiling
#define QT 128        // query rows per block
#define KT 64         // keys per tile
#define QTP (QT + 4)  // padded row length for Qt
#define KTP (KT + 4)  // padded row length (68)

// Scratch (allocation-free rule: __device__ globals)
__device__ float g_Q[(size_t)BATCH * HEADS * SEQ * HD];
__device__ float g_K[(size_t)BATCH * HEADS * SEQ * HD];
__device__ float g_V[(size_t)BATCH * HEADS * SEQ * HD];
__device__ float g_ctx[(size_t)M_TOT * EMB];

// ---------------------------------------------------------------------------
// Projection GEMM: out = X[M_TOT,EMB] @ W[EMB,EMB] + bias
// 128x128 block tile, K-step 16, 256 threads, 8x8 microtile.
// ---------------------------------------------------------------------------
template <bool SPLIT>
__global__ __launch_bounds__(256, 2)
void proj_kernel(const float* __restrict__ X,
                 const float* __restrict__ W,
                 const float* __restrict__ bias,
                 float* __restrict__ out)
{
    __shared__ float As[16][128];
    __shared__ float Bs[16][128];

    const int tid = threadIdx.x;
    const int m0 = blockIdx.y * 128;
    const int n0 = blockIdx.x * 128;
    const int tm = tid >> 4;
    const int tn = tid & 15;

    float acc[8][8];
#pragma unroll
    for (int i = 0; i < 8; ++i)
#pragma unroll
        for (int j = 0; j < 8; ++j) acc[i][j] = 0.f;

    for (int k0 = 0; k0 < EMB; k0 += 16) {
#pragma unroll
        for (int u = 0; u < 2; ++u) {
            int id = tid * 2 + u;
            int r  = id >> 2;
            int c4 = (id & 3) * 4;
            float4 v = *(const float4*)(X + (size_t)(m0 + r) * EMB + k0 + c4);
            As[c4 + 0][r] = v.x;
            As[c4 + 1][r] = v.y;
            As[c4 + 2][r] = v.z;
            As[c4 + 3][r] = v.w;
        }
#pragma unroll
        for (int u = 0; u < 2; ++u) {
            int id = tid * 2 + u;
            int r  = id >> 5;
            int c4 = (id & 31) * 4;
            *(float4*)(&Bs[r][c4]) =
                *(const float4*)(W + (size_t)(k0 + r) * EMB + n0 + c4);
        }
        __syncthreads();

#pragma unroll
        for (int kk = 0; kk < 16; ++kk) {
            float a[8], b[8];
            *(float4*)(a)     = *(const float4*)(&As[kk][tm * 8]);
            *(float4*)(a + 4) = *(const float4*)(&As[kk][tm * 8 + 4]);
            *(float4*)(b)     = *(const float4*)(&Bs[kk][tn * 8]);
            *(float4*)(b + 4) = *(const float4*)(&Bs[kk][tn * 8 + 4]);
#pragma unroll
            for (int i = 0; i < 8; ++i)
#pragma unroll
                for (int j = 0; j < 8; ++j)
                    acc[i][j] = fmaf(a[i], b[j], acc[i][j]);
        }
        __syncthreads();
    }

#pragma unroll
    for (int i = 0; i < 8; ++i) {
        const int row = m0 + tm * 8 + i;
        const int b   = row >> 11;
        const int n   = row & (SEQ - 1);
#pragma unroll
        for (int j = 0; j < 8; ++j) {
            const int col = n0 + tn * 8 + j;
            const float v = acc[i][j] + __ldg(&bias[col]);
            if (SPLIT) {
                const int h  = col >> 6;
                const int dd = col & (HD - 1);
                out[((size_t)(b * HEADS + h) * SEQ + n) * HD + dd] = v;
            } else {
                out[(size_t)row * EMB + col] = v;
            }
        }
    }
}

// ---------------------------------------------------------------------------
// Flash attention v2: GEMM-structured, online softmax.
// Grid: (SEQ/QT, BATCH*HEADS). Block 256 threads (ty=tid>>4 rows, tx=tid&15).
// Per thread: 8 query rows (ty*8..+8) x 4 cols (tx*4..+4).
//   S-GEMM: S[128x64] = Qt(d-major) x Kt(d-major), 32 FMA / 3 LDS.128 per k.
//   softmax stats via shfl over the 16 tx lanes (intra-warp).
//   P staged to smem row-major -> PV-GEMM with broadcast A-loads.
// ---------------------------------------------------------------------------
extern __shared__ float s_dyn[];

__global__ __launch_bounds__(256, 2)
void attn_kernel(const float* __restrict__ Q,
                 const float* __restrict__ K,
                 const float* __restrict__ V,
                 float* __restrict__ ctx)
{
    float* Qt = s_dyn;                       // [HD][QTP]  d-major Q (scaled)
    float* Kt = Qt + HD * QTP;               // [HD][KTP]  d-major K tile
    float* Vs = Kt + HD * KTP;               // [KT][KTP]  row-major V tile
    float* Ps = Vs + KT * KTP;               // [QT][KTP]  row-major P tile

    const int tid = threadIdx.x;
    const int ty  = tid >> 4;                // 0..15 -> 8 rows each
    const int tx  = tid & 15;                // 0..15 -> 4 cols each
    const int bh  = blockIdx.y;
    const int q0  = blockIdx.x * QT;

    const float scale = 0.03125f;            // 1/sqrt(EMB)

    const float* Qb = Q + (size_t)bh * SEQ * HD;
    const float* Kb = K + (size_t)bh * SEQ * HD;
    const float* Vb = V + (size_t)bh * SEQ * HD;

    // ---- Load + transpose Q tile (once), folding in the scale ----
#pragma unroll
    for (int u = 0; u < 8; ++u) {
        int id  = tid + 256 * u;             // 2048 float4 total
        int row = id >> 4;                   // 0..127
        int d4  = (id & 15) * 4;
        float4 v = *(const float4*)(Qb + (size_t)(q0 + row) * HD + d4);
        Qt[(d4 + 0) * QTP + row] = v.x * scale;
        Qt[(d4 + 1) * QTP + row] = v.y * scale;
        Qt[(d4 + 2) * QTP + row] = v.z * scale;
        Qt[(d4 + 3) * QTP + row] = v.w * scale;
    }

    float oacc[8][4];
#pragma unroll
    for (int i = 0; i < 8; ++i)
#pragma unroll
        for (int j = 0; j < 4; ++j) oacc[i][j] = 0.f;
    float mrow[8], lrow[8];
#pragma unroll
    for (int i = 0; i < 8; ++i) { mrow[i] = -1e30f; lrow[i] = 0.f; }

    for (int kt = 0; kt < SEQ; kt += KT) {
        __syncthreads();   // prev iter done with Kt/Vs; Qt ready (first iter)

        // ---- Load K tile transposed (d-major) + V tile (row-major) ----
#pragma unroll
        for (int u = 0; u < 4; ++u) {
            int id  = tid + 256 * u;          // 1024 float4
            int key = id >> 4;                // 0..63
            int d4  = (id & 15) * 4;
            float4 kv = *(const float4*)(Kb + (size_t)(kt + key) * HD + d4);
            Kt[(d4 + 0) * KTP + key] = kv.x;
            Kt[(d4 + 1) * KTP + key] = kv.y;
            Kt[(d4 + 2) * KTP + key] = kv.z;
            Kt[(d4 + 3) * KTP + key] = kv.w;
            float4 vv = *(const float4*)(Vb + (size_t)(kt + key) * HD + d4);
            *(float4*)(&Vs[key * KTP + d4]) = vv;
        }
        __syncthreads();

        // ---- S-GEMM: sacc[8][4] ----
        float sacc[8][4];
#pragma unroll
        for (int i = 0; i < 8; ++i)
#pragma unroll
            for (int j = 0; j < 4; ++j) sacc[i][j] = 0.f;

#pragma unroll 4
        for (int kk = 0; kk < HD; ++kk) {
            float a[8], b[4];
            *(float4*)(a)     = *(const float4*)(&Qt[kk * QTP + ty * 8]);
            *(float4*)(a + 4) = *(const float4*)(&Qt[kk * QTP + ty * 8 + 4]);
            *(float4*)(b)     = *(const float4*)(&Kt[kk * KTP + tx * 4]);
#pragma unroll
            for (int i = 0; i < 8; ++i)
#pragma unroll
                for (int j = 0; j < 4; ++j)
                    sacc[i][j] = fmaf(a[i], b[j], sacc[i][j]);
        }

        // ---- Online softmax over this 64-key slab ----
#pragma unroll
        for (int i = 0; i < 8; ++i) {
            float cm = fmaxf(fmaxf(sacc[i][0], sacc[i][1]),
                             fmaxf(sacc[i][2], sacc[i][3]));
            cm = fmaxf(cm, __shfl_xor_sync(0xffffffffu, cm, 1));
            cm = fmaxf(cm, __shfl_xor_sync(0xffffffffu, cm, 2));
            cm = fmaxf(cm, __shfl_xor_sync(0xffffffffu, cm, 4));
            cm = fmaxf(cm, __shfl_xor_sync(0xffffffffu, cm, 8));
            const float mn = fmaxf(mrow[i], cm);
            const float f  = __expf(mrow[i] - mn);
            float4 p;
            p.x = __expf(sacc[i][0] - mn);
            p.y = __expf(sacc[i][1] - mn);
            p.z = __expf(sacc[i][2] - mn);
            p.w = __expf(sacc[i][3] - mn);
            float sp = p.x + p.y + p.z + p.w;
            sp += __shfl_xor_sync(0xffffffffu, sp, 1);
            sp += __shfl_xor_sync(0xffffffffu, sp, 2);
            sp += __shfl_xor_sync(0xffffffffu, sp, 4);
            sp += __shfl_xor_sync(0xffffffffu, sp, 8);
            lrow[i] = lrow[i] * f + sp;
            mrow[i] = mn;
#pragma unroll
            for (int j = 0; j < 4; ++j) oacc[i][j] *= f;
            *(float4*)(&Ps[(ty * 8 + i) * KTP + tx * 4]) = p;
        }
        __syncwarp();   // Ps rows for this ty are produced within this warp

        // ---- PV-GEMM: oacc += P[128x64] * V[64x64], K4 = 4 ----
#pragma unroll
        for (int k4 = 0; k4 < KT / 4; ++k4) {
            float4 a4[8];
            float4 b4[4];
#pragma unroll
            for (int i = 0; i < 8; ++i)
                a4[i] = *(const float4*)(&Ps[(ty * 8 + i) * KTP + k4 * 4]);
#pragma unroll
            for (int c = 0; c < 4; ++c)
                b4[c] = *(const float4*)(&Vs[(k4 * 4 + c) * KTP + tx * 4]);
#pragma unroll
            for (int i = 0; i < 8; ++i) {
                oacc[i][0] = fmaf(a4[i].x, b4[0].x, oacc[i][0]);
                oacc[i][1] = fmaf(a4[i].x, b4[0].y, oacc[i][1]);
                oacc[i][2] = fmaf(a4[i].x, b4[0].z, oacc[i][2]);
                oacc[i][3] = fmaf(a4[i].x, b4[0].w, oacc[i][3]);
                oacc[i][0] = fmaf(a4[i].y, b4[1].x, oacc[i][0]);
                oacc[i][1] = fmaf(a4[i].y, b4[1].y, oacc[i][1]);
                oacc[i][2] = fmaf(a4[i].y, b4[1].z, oacc[i][2]);
                oacc[i][3] = fmaf(a4[i].y, b4[1].w, oacc[i][3]);
                oacc[i][0] = fmaf(a4[i].z, b4[2].x, oacc[i][0]);
                oacc[i][1] = fmaf(a4[i].z, b4[2].y, oacc[i][1]);
                oacc[i][2] = fmaf(a4[i].z, b4[2].z, oacc[i][2]);
                oacc[i][3] = fmaf(a4[i].z, b4[2].w, oacc[i][3]);
                oacc[i][0] = fmaf(a4[i].w, b4[3].x, oacc[i][0]);
                oacc[i][1] = fmaf(a4[i].w, b4[3].y, oacc[i][1]);
                oacc[i][2] = fmaf(a4[i].w, b4[3].z, oacc[i][2]);
                oacc[i][3] = fmaf(a4[i].w, b4[3].w, oacc[i][3]);
            }
        }
    }

    // ---- Epilogue: normalize, write to ctx [b*SEQ+n][h*HD + d] ----
    const int b = bh / HEADS;
    const int h = bh % HEADS;
#pragma unroll
    for (int i = 0; i < 8; ++i) {
        const float inv = 1.f / lrow[i];
        const int row = q0 + ty * 8 + i;
        float4 v;
        v.x = oacc[i][0] * inv;
        v.y = oacc[i][1] * inv;
        v.z = oacc[i][2] * inv;
        v.w = oacc[i][3] * inv;
        *(float4*)(ctx + (size_t)(b * SEQ + row) * EMB + h * HD + tx * 4) = v;
    }
}

// ---------------------------------------------------------------------------
// Launch
// ---------------------------------------------------------------------------
extern "C" void kernel_launch(void* const* d_in, const int* in_sizes, int n_in,
                              void* d_out, int out_size)
{
    const float* x  = (const float*)d_in[0];
    const float* Wq = (const float*)d_in[1];
    const float* bq = (const float*)d_in[2];
    const float* Wk = (const float*)d_in[3];
    const float* bk = (const float*)d_in[4];
    const float* Wv = (const float*)d_in[5];
    const float* bv = (const float*)d_in[6];
    const float* Wo = (const float*)d_in[7];
    const float* bo = (const float*)d_in[8];
    float* out = (float*)d_out;

    float *Qp, *Kp, *Vp, *Cp;
    cudaGetSymbolAddress((void**)&Qp, g_Q);
    cudaGetSymbolAddress((void**)&Kp, g_K);
    cudaGetSymbolAddress((void**)&Vp, g_V);
    cudaGetSymbolAddress((void**)&Cp, g_ctx);

    const int attn_smem = (HD * QTP + HD * KTP + KT * KTP + QT * KTP) * 4;
    static int configured = 0;
    if (!configured) {
        cudaFuncSetAttribute(attn_kernel,
                             cudaFuncAttributeMaxDynamicSharedMemorySize,
                             attn_smem);
        configured = 1;
    }

    dim3 pgrid(EMB / 128, M_TOT / 128);
    proj_kernel<true><<<pgrid, 256>>>(x, Wq, bq, Qp);
    proj_kernel<true><<<pgrid, 256>>>(x, Wk, bk, Kp);
    proj_kernel<true><<<pgrid, 256>>>(x, Wv, bv, Vp);

    dim3 agrid(SEQ / QT, BATCH * HEADS);
    attn_kernel<<<agrid, 256, attn_smem>>>(Qp, Kp, Vp, Cp);

    proj_kernel<false><<<pgrid, 256>>>(Cp, Wo, bo, out);
}

// round 4
// speedup vs baseline: 3.5974x; 1.3882x over previous
#include <cuda_runtime.h>
#include <cuda_bf16.h>
#include <math_constants.h>
#include <cstdint>

// Problem constants
#define EMB   1024
#define HEADS 16
#define HD    64
#define BATCH 2
#define SEQ   2048
#define M_TOT (BATCH * SEQ)

// Attention tiling
#define QT 128
#define KT 64
#define QTP (QT + 4)
#define KTP (KT + 4)

// Scratch (allocation-free rule: __device__ globals)
__device__ float g_Q[(size_t)BATCH * HEADS * SEQ * HD];
__device__ float g_K[(size_t)BATCH * HEADS * SEQ * HD];
__device__ float g_V[(size_t)BATCH * HEADS * SEQ * HD];
__device__ float g_ctx[(size_t)M_TOT * EMB];

// ---------------------------------------------------------------------------
// Helpers: fp32 -> (bf16 hi, bf16 lo) split, packed pairs for mma fragments
// ---------------------------------------------------------------------------
__device__ __forceinline__ void splitf(float v, unsigned short& h, unsigned short& l)
{
    __nv_bfloat16 hb = __float2bfloat16(v);
    float rv = v - __bfloat162float(hb);
    __nv_bfloat16 lb = __float2bfloat16(rv);
    h = ((__nv_bfloat16_raw)hb).x;
    l = ((__nv_bfloat16_raw)lb).x;
}

__device__ __forceinline__ void split2(float v0, float v1,
                                       unsigned int& hp, unsigned int& lp)
{
    unsigned short h0, l0, h1, l1;
    splitf(v0, h0, l0);
    splitf(v1, h1, l1);
    hp = (unsigned int)h0 | ((unsigned int)h1 << 16);
    lp = (unsigned int)l0 | ((unsigned int)l1 << 16);
}

__device__ __forceinline__ void mma_bf16(float* d,
                                         unsigned int a0, unsigned int a1,
                                         unsigned int a2, unsigned int a3,
                                         unsigned int b0, unsigned int b1)
{
    asm volatile(
        "mma.sync.aligned.m16n8k16.row.col.f32.bf16.bf16.f32 "
        "{%0,%1,%2,%3}, {%4,%5,%6,%7}, {%8,%9}, {%0,%1,%2,%3};\n"
        : "+f"(d[0]), "+f"(d[1]), "+f"(d[2]), "+f"(d[3])
        : "r"(a0), "r"(a1), "r"(a2), "r"(a3), "r"(b0), "r"(b1));
}

// ---------------------------------------------------------------------------
// Projection GEMM on tensor cores (bf16 hi/lo split, fp32 accumulate).
// out = X[M_TOT,EMB] @ W[EMB,EMB] + bias
// Block tile 128x128, K-step 32, 256 threads (8 warps as 2(M) x 4(N)),
// warp tile 64x32, mma.m16n8k16. Three mma per tile: AhBh + AhBl + AlBh.
//
// SMEM layout: k-pairs packed into u32, [k2][m or n] with row stride 132.
// ---------------------------------------------------------------------------
#define KLD 132

template <bool SPLIT>
__global__ __launch_bounds__(256, 2)
void proj_mma_kernel(const float* __restrict__ X,
                     const float* __restrict__ W,
                     const float* __restrict__ bias,
                     float* __restrict__ out)
{
    __shared__ __align__(16) unsigned int Ah2[16 * KLD];
    __shared__ __align__(16) unsigned int Al2[16 * KLD];
    __shared__ __align__(16) unsigned int Bh2[16 * KLD];
    __shared__ __align__(16) unsigned int Bl2[16 * KLD];

    const int tid  = threadIdx.x;
    const int m0   = blockIdx.y * 128;
    const int n0   = blockIdx.x * 128;
    const int lane = tid & 31;
    const int wid  = tid >> 5;
    const int wm   = wid & 1;       // 2 warps along M (64 rows each)
    const int wn   = wid >> 1;      // 4 warps along N (32 cols each)
    const int g    = lane >> 2;     // 0..7
    const int t    = lane & 3;      // 0..3

    float acc[4][4][4];
#pragma unroll
    for (int i = 0; i < 4; ++i)
#pragma unroll
        for (int j = 0; j < 4; ++j)
#pragma unroll
            for (int r = 0; r < 4; ++r) acc[i][j][r] = 0.f;

    for (int k0 = 0; k0 < EMB; k0 += 32) {
        __syncthreads();

        // ---- Stage A tile: X[m0..m0+127][k0..k0+31] -> split bf16, [k2][m] ----
#pragma unroll
        for (int u = 0; u < 4; ++u) {
            int id = tid + 256 * u;            // 1024 float4 jobs
            int r  = id >> 3;                  // 0..127
            int c4 = (id & 7) * 4;             // k offset 0..28
            float4 v = *(const float4*)(X + (size_t)(m0 + r) * EMB + k0 + c4);
            unsigned int h0, l0, h1, l1;
            split2(v.x, v.y, h0, l0);
            split2(v.z, v.w, h1, l1);
            int k2 = c4 >> 1;
            Ah2[k2 * KLD + r]       = h0;
            Ah2[(k2 + 1) * KLD + r] = h1;
            Al2[k2 * KLD + r]       = l0;
            Al2[(k2 + 1) * KLD + r] = l1;
        }

        // ---- Stage B tile: W[k0..k0+31][n0..n0+127] -> split bf16, [k2][n] ----
#pragma unroll
        for (int u = 0; u < 2; ++u) {
            int id = tid + 256 * u;            // 512 jobs
            int k2 = id >> 5;                  // 0..15
            int n4 = (id & 31) * 4;            // 0..124
            float4 w0 = *(const float4*)(W + (size_t)(k0 + 2 * k2) * EMB + n0 + n4);
            float4 w1 = *(const float4*)(W + (size_t)(k0 + 2 * k2 + 1) * EMB + n0 + n4);
            unsigned int hh[4], ll[4];
            unsigned short ha, la, hb, lb;
            splitf(w0.x, ha, la); splitf(w1.x, hb, lb);
            hh[0] = (unsigned int)ha | ((unsigned int)hb << 16);
            ll[0] = (unsigned int)la | ((unsigned int)lb << 16);
            splitf(w0.y, ha, la); splitf(w1.y, hb, lb);
            hh[1] = (unsigned int)ha | ((unsigned int)hb << 16);
            ll[1] = (unsigned int)la | ((unsigned int)lb << 16);
            splitf(w0.z, ha, la); splitf(w1.z, hb, lb);
            hh[2] = (unsigned int)ha | ((unsigned int)hb << 16);
            ll[2] = (unsigned int)la | ((unsigned int)lb << 16);
            splitf(w0.w, ha, la); splitf(w1.w, hb, lb);
            hh[3] = (unsigned int)ha | ((unsigned int)hb << 16);
            ll[3] = (unsigned int)la | ((unsigned int)lb << 16);
            *(uint4*)(&Bh2[k2 * KLD + n4]) = make_uint4(hh[0], hh[1], hh[2], hh[3]);
            *(uint4*)(&Bl2[k2 * KLD + n4]) = make_uint4(ll[0], ll[1], ll[2], ll[3]);
        }
        __syncthreads();

        // ---- Compute: 2 k-steps of 16 ----
#pragma unroll
        for (int ks = 0; ks < 2; ++ks) {
            const int kb = ks * 8 + t;
            unsigned int bh0[4], bh1[4], bl0[4], bl1[4];
#pragma unroll
            for (int nt = 0; nt < 4; ++nt) {
                int cc = wn * 32 + nt * 8 + g;
                bh0[nt] = Bh2[kb * KLD + cc];
                bh1[nt] = Bh2[(kb + 4) * KLD + cc];
                bl0[nt] = Bl2[kb * KLD + cc];
                bl1[nt] = Bl2[(kb + 4) * KLD + cc];
            }
#pragma unroll
            for (int mt = 0; mt < 4; ++mt) {
                int mr = wm * 64 + mt * 16 + g;
                unsigned int a0h = Ah2[kb * KLD + mr];
                unsigned int a1h = Ah2[kb * KLD + mr + 8];
                unsigned int a2h = Ah2[(kb + 4) * KLD + mr];
                unsigned int a3h = Ah2[(kb + 4) * KLD + mr + 8];
                unsigned int a0l = Al2[kb * KLD + mr];
                unsigned int a1l = Al2[kb * KLD + mr + 8];
                unsigned int a2l = Al2[(kb + 4) * KLD + mr];
                unsigned int a3l = Al2[(kb + 4) * KLD + mr + 8];
#pragma unroll
                for (int nt = 0; nt < 4; ++nt) {
                    mma_bf16(acc[mt][nt], a0h, a1h, a2h, a3h, bh0[nt], bh1[nt]);
                    mma_bf16(acc[mt][nt], a0h, a1h, a2h, a3h, bl0[nt], bl1[nt]);
                    mma_bf16(acc[mt][nt], a0l, a1l, a2l, a3l, bh0[nt], bh1[nt]);
                }
            }
        }
    }

    // ---- Epilogue: bias + store (optionally head-scattered) ----
#pragma unroll
    for (int mt = 0; mt < 4; ++mt) {
#pragma unroll
        for (int nt = 0; nt < 4; ++nt) {
            const int row0 = m0 + wm * 64 + mt * 16 + g;
            const int col  = n0 + wn * 32 + nt * 8 + t * 2;
            const float b0v = __ldg(&bias[col]);
            const float b1v = __ldg(&bias[col + 1]);
#pragma unroll
            for (int half = 0; half < 2; ++half) {
                const int row = row0 + half * 8;
                float2 v;
                v.x = acc[mt][nt][half * 2 + 0] + b0v;
                v.y = acc[mt][nt][half * 2 + 1] + b1v;
                if (SPLIT) {
                    const int b  = row >> 11;
                    const int n  = row & (SEQ - 1);
                    const int h  = col >> 6;
                    const int dd = col & (HD - 1);
                    *(float2*)(out + ((size_t)(b * HEADS + h) * SEQ + n) * HD + dd) = v;
                } else {
                    *(float2*)(out + (size_t)row * EMB + col) = v;
                }
            }
        }
    }
}

// ---------------------------------------------------------------------------
// Flash attention (unchanged from R2): GEMM-structured fp32, online softmax.
// ---------------------------------------------------------------------------
extern __shared__ float s_dyn[];

__global__ __launch_bounds__(256, 2)
void attn_kernel(const float* __restrict__ Q,
                 const float* __restrict__ K,
                 const float* __restrict__ V,
                 float* __restrict__ ctx)
{
    float* Qt = s_dyn;
    float* Kt = Qt + HD * QTP;
    float* Vs = Kt + HD * KTP;
    float* Ps = Vs + KT * KTP;

    const int tid = threadIdx.x;
    const int ty  = tid >> 4;
    const int tx  = tid & 15;
    const int bh  = blockIdx.y;
    const int q0  = blockIdx.x * QT;

    const float scale = 0.03125f;

    const float* Qb = Q + (size_t)bh * SEQ * HD;
    const float* Kb = K + (size_t)bh * SEQ * HD;
    const float* Vb = V + (size_t)bh * SEQ * HD;

#pragma unroll
    for (int u = 0; u < 8; ++u) {
        int id  = tid + 256 * u;
        int row = id >> 4;
        int d4  = (id & 15) * 4;
        float4 v = *(const float4*)(Qb + (size_t)(q0 + row) * HD + d4);
        Qt[(d4 + 0) * QTP + row] = v.x * scale;
        Qt[(d4 + 1) * QTP + row] = v.y * scale;
        Qt[(d4 + 2) * QTP + row] = v.z * scale;
        Qt[(d4 + 3) * QTP + row] = v.w * scale;
    }

    float oacc[8][4];
#pragma unroll
    for (int i = 0; i < 8; ++i)
#pragma unroll
        for (int j = 0; j < 4; ++j) oacc[i][j] = 0.f;
    float mrow[8], lrow[8];
#pragma unroll
    for (int i = 0; i < 8; ++i) { mrow[i] = -1e30f; lrow[i] = 0.f; }

    for (int kt = 0; kt < SEQ; kt += KT) {
        __syncthreads();

#pragma unroll
        for (int u = 0; u < 4; ++u) {
            int id  = tid + 256 * u;
            int key = id >> 4;
            int d4  = (id & 15) * 4;
            float4 kv = *(const float4*)(Kb + (size_t)(kt + key) * HD + d4);
            Kt[(d4 + 0) * KTP + key] = kv.x;
            Kt[(d4 + 1) * KTP + key] = kv.y;
            Kt[(d4 + 2) * KTP + key] = kv.z;
            Kt[(d4 + 3) * KTP + key] = kv.w;
            float4 vv = *(const float4*)(Vb + (size_t)(kt + key) * HD + d4);
            *(float4*)(&Vs[key * KTP + d4]) = vv;
        }
        __syncthreads();

        float sacc[8][4];
#pragma unroll
        for (int i = 0; i < 8; ++i)
#pragma unroll
            for (int j = 0; j < 4; ++j) sacc[i][j] = 0.f;

#pragma unroll 4
        for (int kk = 0; kk < HD; ++kk) {
            float a[8], b[4];
            *(float4*)(a)     = *(const float4*)(&Qt[kk * QTP + ty * 8]);
            *(float4*)(a + 4) = *(const float4*)(&Qt[kk * QTP + ty * 8 + 4]);
            *(float4*)(b)     = *(const float4*)(&Kt[kk * KTP + tx * 4]);
#pragma unroll
            for (int i = 0; i < 8; ++i)
#pragma unroll
                for (int j = 0; j < 4; ++j)
                    sacc[i][j] = fmaf(a[i], b[j], sacc[i][j]);
        }

#pragma unroll
        for (int i = 0; i < 8; ++i) {
            float cm = fmaxf(fmaxf(sacc[i][0], sacc[i][1]),
                             fmaxf(sacc[i][2], sacc[i][3]));
            cm = fmaxf(cm, __shfl_xor_sync(0xffffffffu, cm, 1));
            cm = fmaxf(cm, __shfl_xor_sync(0xffffffffu, cm, 2));
            cm = fmaxf(cm, __shfl_xor_sync(0xffffffffu, cm, 4));
            cm = fmaxf(cm, __shfl_xor_sync(0xffffffffu, cm, 8));
            const float mn = fmaxf(mrow[i], cm);
            const float f  = __expf(mrow[i] - mn);
            float4 p;
            p.x = __expf(sacc[i][0] - mn);
            p.y = __expf(sacc[i][1] - mn);
            p.z = __expf(sacc[i][2] - mn);
            p.w = __expf(sacc[i][3] - mn);
            float sp = p.x + p.y + p.z + p.w;
            sp += __shfl_xor_sync(0xffffffffu, sp, 1);
            sp += __shfl_xor_sync(0xffffffffu, sp, 2);
            sp += __shfl_xor_sync(0xffffffffu, sp, 4);
            sp += __shfl_xor_sync(0xffffffffu, sp, 8);
            lrow[i] = lrow[i] * f + sp;
            mrow[i] = mn;
#pragma unroll
            for (int j = 0; j < 4; ++j) oacc[i][j] *= f;
            *(float4*)(&Ps[(ty * 8 + i) * KTP + tx * 4]) = p;
        }
        __syncwarp();

#pragma unroll
        for (int k4 = 0; k4 < KT / 4; ++k4) {
            float4 a4[8];
            float4 b4[4];
#pragma unroll
            for (int i = 0; i < 8; ++i)
                a4[i] = *(const float4*)(&Ps[(ty * 8 + i) * KTP + k4 * 4]);
#pragma unroll
            for (int c = 0; c < 4; ++c)
                b4[c] = *(const float4*)(&Vs[(k4 * 4 + c) * KTP + tx * 4]);
#pragma unroll
            for (int i = 0; i < 8; ++i) {
                oacc[i][0] = fmaf(a4[i].x, b4[0].x, oacc[i][0]);
                oacc[i][1] = fmaf(a4[i].x, b4[0].y, oacc[i][1]);
                oacc[i][2] = fmaf(a4[i].x, b4[0].z, oacc[i][2]);
                oacc[i][3] = fmaf(a4[i].x, b4[0].w, oacc[i][3]);
                oacc[i][0] = fmaf(a4[i].y, b4[1].x, oacc[i][0]);
                oacc[i][1] = fmaf(a4[i].y, b4[1].y, oacc[i][1]);
                oacc[i][2] = fmaf(a4[i].y, b4[1].z, oacc[i][2]);
                oacc[i][3] = fmaf(a4[i].y, b4[1].w, oacc[i][3]);
                oacc[i][0] = fmaf(a4[i].z, b4[2].x, oacc[i][0]);
                oacc[i][1] = fmaf(a4[i].z, b4[2].y, oacc[i][1]);
                oacc[i][2] = fmaf(a4[i].z, b4[2].z, oacc[i][2]);
                oacc[i][3] = fmaf(a4[i].z, b4[2].w, oacc[i][3]);
                oacc[i][0] = fmaf(a4[i].w, b4[3].x, oacc[i][0]);
                oacc[i][1] = fmaf(a4[i].w, b4[3].y, oacc[i][1]);
                oacc[i][2] = fmaf(a4[i].w, b4[3].z, oacc[i][2]);
                oacc[i][3] = fmaf(a4[i].w, b4[3].w, oacc[i][3]);
            }
        }
    }

    const int b = bh / HEADS;
    const int h = bh % HEADS;
#pragma unroll
    for (int i = 0; i < 8; ++i) {
        const float inv = 1.f / lrow[i];
        const int row = q0 + ty * 8 + i;
        float4 v;
        v.x = oacc[i][0] * inv;
        v.y = oacc[i][1] * inv;
        v.z = oacc[i][2] * inv;
        v.w = oacc[i][3] * inv;
        *(float4*)(ctx + (size_t)(b * SEQ + row) * EMB + h * HD + tx * 4) = v;
    }
}

// ---------------------------------------------------------------------------
// Launch
// ---------------------------------------------------------------------------
extern "C" void kernel_launch(void* const* d_in, const int* in_sizes, int n_in,
                              void* d_out, int out_size)
{
    const float* x  = (const float*)d_in[0];
    const float* Wq = (const float*)d_in[1];
    const float* bq = (const float*)d_in[2];
    const float* Wk = (const float*)d_in[3];
    const float* bk = (const float*)d_in[4];
    const float* Wv = (const float*)d_in[5];
    const float* bv = (const float*)d_in[6];
    const float* Wo = (const float*)d_in[7];
    const float* bo = (const float*)d_in[8];
    float* out = (float*)d_out;

    float *Qp, *Kp, *Vp, *Cp;
    cudaGetSymbolAddress((void**)&Qp, g_Q);
    cudaGetSymbolAddress((void**)&Kp, g_K);
    cudaGetSymbolAddress((void**)&Vp, g_V);
    cudaGetSymbolAddress((void**)&Cp, g_ctx);

    const int attn_smem = (HD * QTP + HD * KTP + KT * KTP + QT * KTP) * 4;
    static int configured = 0;
    if (!configured) {
        cudaFuncSetAttribute(attn_kernel,
                             cudaFuncAttributeMaxDynamicSharedMemorySize,
                             attn_smem);
        configured = 1;
    }

    dim3 pgrid(EMB / 128, M_TOT / 128);
    proj_mma_kernel<true><<<pgrid, 256>>>(x, Wq, bq, Qp);
    proj_mma_kernel<true><<<pgrid, 256>>>(x, Wk, bk, Kp);
    proj_mma_kernel<true><<<pgrid, 256>>>(x, Wv, bv, Vp);

    dim3 agrid(SEQ / QT, BATCH * HEADS);
    attn_kernel<<<agrid, 256, attn_smem>>>(Qp, Kp, Vp, Cp);

    proj_mma_kernel<false><<<pgrid, 256>>>(Cp, Wo, bo, out);
}

// round 5
// speedup vs baseline: 5.6453x; 1.5693x over previous
#include <cuda_runtime.h>
#include <cuda_bf16.h>
#include <math_constants.h>
#include <cstdint>

// Problem constants
#define EMB   1024
#define HEADS 16
#define HD    64
#define BATCH 2
#define SEQ   2048
#define M_TOT (BATCH * SEQ)

// Scratch (allocation-free rule: __device__ globals)
__device__ float g_Q[(size_t)BATCH * HEADS * SEQ * HD];
__device__ float g_K[(size_t)BATCH * HEADS * SEQ * HD];
__device__ float g_V[(size_t)BATCH * HEADS * SEQ * HD];
__device__ float g_ctx[(size_t)M_TOT * EMB];

// ---------------------------------------------------------------------------
// Helpers: fp32 -> (bf16 hi, bf16 lo) split, packed pairs for mma fragments
// ---------------------------------------------------------------------------
__device__ __forceinline__ void splitf(float v, unsigned short& h, unsigned short& l)
{
    __nv_bfloat16 hb = __float2bfloat16(v);
    float rv = v - __bfloat162float(hb);
    __nv_bfloat16 lb = __float2bfloat16(rv);
    h = ((__nv_bfloat16_raw)hb).x;
    l = ((__nv_bfloat16_raw)lb).x;
}

__device__ __forceinline__ void split2(float v0, float v1,
                                       unsigned int& hp, unsigned int& lp)
{
    unsigned short h0, l0, h1, l1;
    splitf(v0, h0, l0);
    splitf(v1, h1, l1);
    hp = (unsigned int)h0 | ((unsigned int)h1 << 16);
    lp = (unsigned int)l0 | ((unsigned int)l1 << 16);
}

__device__ __forceinline__ void mma_bf16(float* d,
                                         unsigned int a0, unsigned int a1,
                                         unsigned int a2, unsigned int a3,
                                         unsigned int b0, unsigned int b1)
{
    asm volatile(
        "mma.sync.aligned.m16n8k16.row.col.f32.bf16.bf16.f32 "
        "{%0,%1,%2,%3}, {%4,%5,%6,%7}, {%8,%9}, {%0,%1,%2,%3};\n"
        : "+f"(d[0]), "+f"(d[1]), "+f"(d[2]), "+f"(d[3])
        : "r"(a0), "r"(a1), "r"(a2), "r"(a3), "r"(b0), "r"(b1));
}

// ---------------------------------------------------------------------------
// Projection GEMM on tensor cores (bf16 hi/lo split, fp32 accumulate).
// (unchanged from R4 — measured ~97us per GEMM)
// ---------------------------------------------------------------------------
#define KLD 132

template <bool SPLIT>
__global__ __launch_bounds__(256, 2)
void proj_mma_kernel(const float* __restrict__ X,
                     const float* __restrict__ W,
                     const float* __restrict__ bias,
                     float* __restrict__ out)
{
    __shared__ __align__(16) unsigned int Ah2[16 * KLD];
    __shared__ __align__(16) unsigned int Al2[16 * KLD];
    __shared__ __align__(16) unsigned int Bh2[16 * KLD];
    __shared__ __align__(16) unsigned int Bl2[16 * KLD];

    const int tid  = threadIdx.x;
    const int m0   = blockIdx.y * 128;
    const int n0   = blockIdx.x * 128;
    const int lane = tid & 31;
    const int wid  = tid >> 5;
    const int wm   = wid & 1;
    const int wn   = wid >> 1;
    const int g    = lane >> 2;
    const int t    = lane & 3;

    float acc[4][4][4];
#pragma unroll
    for (int i = 0; i < 4; ++i)
#pragma unroll
        for (int j = 0; j < 4; ++j)
#pragma unroll
            for (int r = 0; r < 4; ++r) acc[i][j][r] = 0.f;

    for (int k0 = 0; k0 < EMB; k0 += 32) {
        __syncthreads();

#pragma unroll
        for (int u = 0; u < 4; ++u) {
            int id = tid + 256 * u;
            int r  = id >> 3;
            int c4 = (id & 7) * 4;
            float4 v = *(const float4*)(X + (size_t)(m0 + r) * EMB + k0 + c4);
            unsigned int h0, l0, h1, l1;
            split2(v.x, v.y, h0, l0);
            split2(v.z, v.w, h1, l1);
            int k2 = c4 >> 1;
            Ah2[k2 * KLD + r]       = h0;
            Ah2[(k2 + 1) * KLD + r] = h1;
            Al2[k2 * KLD + r]       = l0;
            Al2[(k2 + 1) * KLD + r] = l1;
        }

#pragma unroll
        for (int u = 0; u < 2; ++u) {
            int id = tid + 256 * u;
            int k2 = id >> 5;
            int n4 = (id & 31) * 4;
            float4 w0 = *(const float4*)(W + (size_t)(k0 + 2 * k2) * EMB + n0 + n4);
            float4 w1 = *(const float4*)(W + (size_t)(k0 + 2 * k2 + 1) * EMB + n0 + n4);
            unsigned int hh[4], ll[4];
            unsigned short ha, la, hb, lb;
            splitf(w0.x, ha, la); splitf(w1.x, hb, lb);
            hh[0] = (unsigned int)ha | ((unsigned int)hb << 16);
            ll[0] = (unsigned int)la | ((unsigned int)lb << 16);
            splitf(w0.y, ha, la); splitf(w1.y, hb, lb);
            hh[1] = (unsigned int)ha | ((unsigned int)hb << 16);
            ll[1] = (unsigned int)la | ((unsigned int)lb << 16);
            splitf(w0.z, ha, la); splitf(w1.z, hb, lb);
            hh[2] = (unsigned int)ha | ((unsigned int)hb << 16);
            ll[2] = (unsigned int)la | ((unsigned int)lb << 16);
            splitf(w0.w, ha, la); splitf(w1.w, hb, lb);
            hh[3] = (unsigned int)ha | ((unsigned int)hb << 16);
            ll[3] = (unsigned int)la | ((unsigned int)lb << 16);
            *(uint4*)(&Bh2[k2 * KLD + n4]) = make_uint4(hh[0], hh[1], hh[2], hh[3]);
            *(uint4*)(&Bl2[k2 * KLD + n4]) = make_uint4(ll[0], ll[1], ll[2], ll[3]);
        }
        __syncthreads();

#pragma unroll
        for (int ks = 0; ks < 2; ++ks) {
            const int kb = ks * 8 + t;
            unsigned int bh0[4], bh1[4], bl0[4], bl1[4];
#pragma unroll
            for (int nt = 0; nt < 4; ++nt) {
                int cc = wn * 32 + nt * 8 + g;
                bh0[nt] = Bh2[kb * KLD + cc];
                bh1[nt] = Bh2[(kb + 4) * KLD + cc];
                bl0[nt] = Bl2[kb * KLD + cc];
                bl1[nt] = Bl2[(kb + 4) * KLD + cc];
            }
#pragma unroll
            for (int mt = 0; mt < 4; ++mt) {
                int mr = wm * 64 + mt * 16 + g;
                unsigned int a0h = Ah2[kb * KLD + mr];
                unsigned int a1h = Ah2[kb * KLD + mr + 8];
                unsigned int a2h = Ah2[(kb + 4) * KLD + mr];
                unsigned int a3h = Ah2[(kb + 4) * KLD + mr + 8];
                unsigned int a0l = Al2[kb * KLD + mr];
                unsigned int a1l = Al2[kb * KLD + mr + 8];
                unsigned int a2l = Al2[(kb + 4) * KLD + mr];
                unsigned int a3l = Al2[(kb + 4) * KLD + mr + 8];
#pragma unroll
                for (int nt = 0; nt < 4; ++nt) {
                    mma_bf16(acc[mt][nt], a0h, a1h, a2h, a3h, bh0[nt], bh1[nt]);
                    mma_bf16(acc[mt][nt], a0h, a1h, a2h, a3h, bl0[nt], bl1[nt]);
                    mma_bf16(acc[mt][nt], a0l, a1l, a2l, a3l, bh0[nt], bh1[nt]);
                }
            }
        }
    }

#pragma unroll
    for (int mt = 0; mt < 4; ++mt) {
#pragma unroll
        for (int nt = 0; nt < 4; ++nt) {
            const int row0 = m0 + wm * 64 + mt * 16 + g;
            const int col  = n0 + wn * 32 + nt * 8 + t * 2;
            const float b0v = __ldg(&bias[col]);
            const float b1v = __ldg(&bias[col + 1]);
#pragma unroll
            for (int half = 0; half < 2; ++half) {
                const int row = row0 + half * 8;
                float2 v;
                v.x = acc[mt][nt][half * 2 + 0] + b0v;
                v.y = acc[mt][nt][half * 2 + 1] + b1v;
                if (SPLIT) {
                    const int b  = row >> 11;
                    const int n  = row & (SEQ - 1);
                    const int h  = col >> 6;
                    const int dd = col & (HD - 1);
                    *(float2*)(out + ((size_t)(b * HEADS + h) * SEQ + n) * HD + dd) = v;
                } else {
                    *(float2*)(out + (size_t)row * EMB + col) = v;
                }
            }
        }
    }
}

// ---------------------------------------------------------------------------
// Flash attention on tensor cores (bf16 hi/lo split mma, fp32 softmax).
// Grid: (SEQ/128, BATCH*HEADS). 256 threads = 8 warps; warp owns 16 q-rows.
// Q fragments resident in registers. K tile [key][d2] (stride 36),
// V tile [key2][d] (stride 72) — both conflict-free for B-fragment loads.
// S C-fragments repack register-locally into PV A-fragments.
// ---------------------------------------------------------------------------
#define QLD 36
#define VLD 72

struct AttnSmem {
    union {
        struct { unsigned int h[128 * QLD]; unsigned int l[128 * QLD]; } q;
        struct {
            unsigned int kh[64 * QLD]; unsigned int kl[64 * QLD];
            unsigned int vh[32 * VLD]; unsigned int vl[32 * VLD];
        } kv;
    };
};

__global__ __launch_bounds__(256)
void attn_mma_kernel(const float* __restrict__ Q,
                     const float* __restrict__ K,
                     const float* __restrict__ V,
                     float* __restrict__ ctx)
{
    __shared__ __align__(16) AttnSmem sm;

    const int tid  = threadIdx.x;
    const int w    = tid >> 5;
    const int lane = tid & 31;
    const int g    = lane >> 2;       // 0..7
    const int t    = lane & 3;        // 0..3
    const int bh   = blockIdx.y;
    const int q0   = blockIdx.x * 128;
    const float scale = 0.03125f;     // 1/sqrt(EMB)

    const float* Qb = Q + (size_t)bh * SEQ * HD;
    const float* Kb = K + (size_t)bh * SEQ * HD;
    const float* Vb = V + (size_t)bh * SEQ * HD;

    // ---- Stage Q (scaled, split) into smem: [row][d2] stride QLD ----
#pragma unroll
    for (int u = 0; u < 8; ++u) {
        int id  = tid + 256 * u;       // 2048 jobs
        int row = id >> 4;             // 0..127
        int d4  = (id & 15) * 4;
        float4 v = *(const float4*)(Qb + (size_t)(q0 + row) * HD + d4);
        unsigned int h0, l0, h1, l1;
        split2(v.x * scale, v.y * scale, h0, l0);
        split2(v.z * scale, v.w * scale, h1, l1);
        int d2 = (id & 15) * 2;
        sm.q.h[row * QLD + d2]     = h0;
        sm.q.h[row * QLD + d2 + 1] = h1;
        sm.q.l[row * QLD + d2]     = l0;
        sm.q.l[row * QLD + d2 + 1] = l1;
    }
    __syncthreads();

    // ---- Extract Q A-fragments to registers ----
    unsigned int qh[4][4], ql[4][4];
    const int wq = w * 16;
#pragma unroll
    for (int ks = 0; ks < 4; ++ks) {
        int b0 = (wq + g) * QLD + ks * 8 + t;
        int b1 = (wq + g + 8) * QLD + ks * 8 + t;
        qh[ks][0] = sm.q.h[b0];     qh[ks][1] = sm.q.h[b1];
        qh[ks][2] = sm.q.h[b0 + 4]; qh[ks][3] = sm.q.h[b1 + 4];
        ql[ks][0] = sm.q.l[b0];     ql[ks][1] = sm.q.l[b1];
        ql[ks][2] = sm.q.l[b0 + 4]; ql[ks][3] = sm.q.l[b1 + 4];
    }
    __syncthreads();   // q region about to be reused for K/V

    float oacc[8][4];
#pragma unroll
    for (int j = 0; j < 8; ++j)
#pragma unroll
        for (int r = 0; r < 4; ++r) oacc[j][r] = 0.f;
    float m1 = -1e30f, m2 = -1e30f, l1s = 0.f, l2s = 0.f;

    for (int kt = 0; kt < SEQ; kt += 64) {
        // ---- Stage K tile: [key][d2] split ----
#pragma unroll
        for (int u = 0; u < 4; ++u) {
            int id  = tid + 256 * u;     // 1024 jobs
            int key = id >> 4;           // 0..63
            int d4  = (id & 15) * 4;
            float4 v = *(const float4*)(Kb + (size_t)(kt + key) * HD + d4);
            unsigned int h0, l0, h1, l1;
            split2(v.x, v.y, h0, l0);
            split2(v.z, v.w, h1, l1);
            int d2 = (id & 15) * 2;
            sm.kv.kh[key * QLD + d2]     = h0;
            sm.kv.kh[key * QLD + d2 + 1] = h1;
            sm.kv.kl[key * QLD + d2]     = l0;
            sm.kv.kl[key * QLD + d2 + 1] = l1;
        }
        // ---- Stage V tile: [key2][d] split (pairs along keys) ----
#pragma unroll
        for (int u = 0; u < 2; ++u) {
            int id = tid + 256 * u;      // 512 jobs
            int k2 = id >> 4;            // 0..31
            int d4 = (id & 15) * 4;
            float4 v0 = *(const float4*)(Vb + (size_t)(kt + 2 * k2) * HD + d4);
            float4 v1 = *(const float4*)(Vb + (size_t)(kt + 2 * k2 + 1) * HD + d4);
            unsigned int hh[4], ll[4];
            unsigned short ha, la, hb, lb;
            splitf(v0.x, ha, la); splitf(v1.x, hb, lb);
            hh[0] = (unsigned int)ha | ((unsigned int)hb << 16);
            ll[0] = (unsigned int)la | ((unsigned int)lb << 16);
            splitf(v0.y, ha, la); splitf(v1.y, hb, lb);
            hh[1] = (unsigned int)ha | ((unsigned int)hb << 16);
            ll[1] = (unsigned int)la | ((unsigned int)lb << 16);
            splitf(v0.z, ha, la); splitf(v1.z, hb, lb);
            hh[2] = (unsigned int)ha | ((unsigned int)hb << 16);
            ll[2] = (unsigned int)la | ((unsigned int)lb << 16);
            splitf(v0.w, ha, la); splitf(v1.w, hb, lb);
            hh[3] = (unsigned int)ha | ((unsigned int)hb << 16);
            ll[3] = (unsigned int)la | ((unsigned int)lb << 16);
            *(uint4*)(&sm.kv.vh[k2 * VLD + d4]) = make_uint4(hh[0], hh[1], hh[2], hh[3]);
            *(uint4*)(&sm.kv.vl[k2 * VLD + d4]) = make_uint4(ll[0], ll[1], ll[2], ll[3]);
        }
        __syncthreads();

        // ---- S-GEMM: sacc[8 n-tiles][4] = Q x K^T (split, 3 mma) ----
        float sacc[8][4];
#pragma unroll
        for (int j = 0; j < 8; ++j)
#pragma unroll
            for (int r = 0; r < 4; ++r) sacc[j][r] = 0.f;

#pragma unroll
        for (int ks = 0; ks < 4; ++ks) {
#pragma unroll
            for (int j = 0; j < 8; ++j) {
                int ka = (8 * j + g) * QLD + ks * 8 + t;
                unsigned int bh0 = sm.kv.kh[ka], bh1 = sm.kv.kh[ka + 4];
                unsigned int bl0 = sm.kv.kl[ka], bl1 = sm.kv.kl[ka + 4];
                mma_bf16(sacc[j], qh[ks][0], qh[ks][1], qh[ks][2], qh[ks][3], bh0, bh1);
                mma_bf16(sacc[j], qh[ks][0], qh[ks][1], qh[ks][2], qh[ks][3], bl0, bl1);
                mma_bf16(sacc[j], ql[ks][0], ql[ks][1], ql[ks][2], ql[ks][3], bh0, bh1);
            }
        }

        // ---- Online softmax on fragments (rows g and g+8) ----
        float cm1 = -1e30f, cm2 = -1e30f;
#pragma unroll
        for (int j = 0; j < 8; ++j) {
            cm1 = fmaxf(cm1, fmaxf(sacc[j][0], sacc[j][1]));
            cm2 = fmaxf(cm2, fmaxf(sacc[j][2], sacc[j][3]));
        }
        cm1 = fmaxf(cm1, __shfl_xor_sync(0xffffffffu, cm1, 1));
        cm1 = fmaxf(cm1, __shfl_xor_sync(0xffffffffu, cm1, 2));
        cm2 = fmaxf(cm2, __shfl_xor_sync(0xffffffffu, cm2, 1));
        cm2 = fmaxf(cm2, __shfl_xor_sync(0xffffffffu, cm2, 2));
        const float mn1 = fmaxf(m1, cm1);
        const float mn2 = fmaxf(m2, cm2);
        const float f1 = __expf(m1 - mn1);
        const float f2 = __expf(m2 - mn2);
        m1 = mn1; m2 = mn2;

        float sp1 = 0.f, sp2 = 0.f;
#pragma unroll
        for (int j = 0; j < 8; ++j) {
            sacc[j][0] = __expf(sacc[j][0] - mn1);
            sacc[j][1] = __expf(sacc[j][1] - mn1);
            sacc[j][2] = __expf(sacc[j][2] - mn2);
            sacc[j][3] = __expf(sacc[j][3] - mn2);
            sp1 += sacc[j][0] + sacc[j][1];
            sp2 += sacc[j][2] + sacc[j][3];
        }
        sp1 += __shfl_xor_sync(0xffffffffu, sp1, 1);
        sp1 += __shfl_xor_sync(0xffffffffu, sp1, 2);
        sp2 += __shfl_xor_sync(0xffffffffu, sp2, 1);
        sp2 += __shfl_xor_sync(0xffffffffu, sp2, 2);
        l1s = l1s * f1 + sp1;
        l2s = l2s * f2 + sp2;

#pragma unroll
        for (int j = 0; j < 8; ++j) {
            oacc[j][0] *= f1; oacc[j][1] *= f1;
            oacc[j][2] *= f2; oacc[j][3] *= f2;
        }

        // ---- PV-GEMM: oacc += P x V (split, 3 mma) ----
#pragma unroll
        for (int s = 0; s < 4; ++s) {
            unsigned int a0h, a0l, a1h, a1l, a2h, a2l, a3h, a3l;
            split2(sacc[2 * s][0],     sacc[2 * s][1],     a0h, a0l);
            split2(sacc[2 * s][2],     sacc[2 * s][3],     a1h, a1l);
            split2(sacc[2 * s + 1][0], sacc[2 * s + 1][1], a2h, a2l);
            split2(sacc[2 * s + 1][2], sacc[2 * s + 1][3], a3h, a3l);
#pragma unroll
            for (int j = 0; j < 8; ++j) {
                int va = (8 * s + t) * VLD + 8 * j + g;
                unsigned int vh0 = sm.kv.vh[va], vh1 = sm.kv.vh[va + 4 * VLD];
                unsigned int vl0 = sm.kv.vl[va], vl1 = sm.kv.vl[va + 4 * VLD];
                mma_bf16(oacc[j], a0h, a1h, a2h, a3h, vh0, vh1);
                mma_bf16(oacc[j], a0h, a1h, a2h, a3h, vl0, vl1);
                mma_bf16(oacc[j], a0l, a1l, a2l, a3l, vh0, vh1);
            }
        }
        __syncthreads();   // done with K/V tiles before next staging
    }

    // ---- Epilogue: normalize + write ctx [b*SEQ+n][h*HD + d] ----
    const float inv1 = 1.f / l1s;
    const float inv2 = 1.f / l2s;
    const int b = bh >> 4;
    const int h = bh & 15;
    const int row1 = q0 + w * 16 + g;
    const int row2 = row1 + 8;
#pragma unroll
    for (int j = 0; j < 8; ++j) {
        const int col = h * HD + 8 * j + 2 * t;
        float2 v1w, v2w;
        v1w.x = oacc[j][0] * inv1; v1w.y = oacc[j][1] * inv1;
        v2w.x = oacc[j][2] * inv2; v2w.y = oacc[j][3] * inv2;
        *(float2*)(ctx + (size_t)(b * SEQ + row1) * EMB + col) = v1w;
        *(float2*)(ctx + (size_t)(b * SEQ + row2) * EMB + col) = v2w;
    }
}

// ---------------------------------------------------------------------------
// Launch
// ---------------------------------------------------------------------------
extern "C" void kernel_launch(void* const* d_in, const int* in_sizes, int n_in,
                              void* d_out, int out_size)
{
    const float* x  = (const float*)d_in[0];
    const float* Wq = (const float*)d_in[1];
    const float* bq = (const float*)d_in[2];
    const float* Wk = (const float*)d_in[3];
    const float* bk = (const float*)d_in[4];
    const float* Wv = (const float*)d_in[5];
    const float* bv = (const float*)d_in[6];
    const float* Wo = (const float*)d_in[7];
    const float* bo = (const float*)d_in[8];
    float* out = (float*)d_out;

    float *Qp, *Kp, *Vp, *Cp;
    cudaGetSymbolAddress((void**)&Qp, g_Q);
    cudaGetSymbolAddress((void**)&Kp, g_K);
    cudaGetSymbolAddress((void**)&Vp, g_V);
    cudaGetSymbolAddress((void**)&Cp, g_ctx);

    dim3 pgrid(EMB / 128, M_TOT / 128);
    proj_mma_kernel<true><<<pgrid, 256>>>(x, Wq, bq, Qp);
    proj_mma_kernel<true><<<pgrid, 256>>>(x, Wk, bk, Kp);
    proj_mma_kernel<true><<<pgrid, 256>>>(x, Wv, bv, Vp);

    dim3 agrid(SEQ / 128, BATCH * HEADS);
    attn_mma_kernel<<<agrid, 256>>>(Qp, Kp, Vp, Cp);

    proj_mma_kernel<false><<<pgrid, 256>>>(Cp, Wo, bo, out);
}